// round 6
// baseline (speedup 1.0000x reference)
#include <cuda_runtime.h>
#include <cuda_fp16.h>
#include <mma.h>
#include <math.h>
#include <cstdint>

using namespace nvcuda;

#define S_LEN 2048
#define DM    1024
#define NH    16
#define HD    64

// Scratch (allocation-guard rules: __device__ globals).
__device__ __half g_xh[S_LEN * DM];
__device__ __half g_wh[3][DM * DM];
__device__ __half g_qh[S_LEN * DM];
__device__ __half g_kh[S_LEN * DM];
__device__ __half g_vh[S_LEN * DM];
__device__ float  g_psum[NH * S_LEN * 16];   // per-(row, ktile) partial sums
__device__ float  g_rinv[NH * S_LEN];        // 1 / rowsum

// ---------------------------------------------------------------------------
// fp32 -> fp16 converters.
// ---------------------------------------------------------------------------
__device__ __forceinline__ void cvt4(const float* __restrict__ src,
                                     __half* __restrict__ dst, size_t i)
{
    float4 v = ((const float4*)src)[i];
    __half2 a = __floats2half2_rn(v.x, v.y);
    __half2 b = __floats2half2_rn(v.z, v.w);
    uint2 u;
    u.x = *(const uint32_t*)&a;
    u.y = *(const uint32_t*)&b;
    ((uint2*)dst)[i] = u;
}

__global__ __launch_bounds__(256) void cvt_x_kernel(const float* __restrict__ X)
{
    cvt4(X, g_xh, (size_t)blockIdx.x * 256 + threadIdx.x);
}

__global__ __launch_bounds__(256) void cvt_w_kernel(
    const float* __restrict__ Wq, const float* __restrict__ Wk,
    const float* __restrict__ Wv)
{
    const float* src = (blockIdx.z == 0) ? Wq : (blockIdx.z == 1) ? Wk : Wv;
    cvt4(src, g_wh[blockIdx.z], (size_t)blockIdx.x * 256 + threadIdx.x);
}

// ---------------------------------------------------------------------------
// Kernel 1: QKV projection, fp16 in / fp32 accum / fp16 out (smem-staged).
// Yh = Xh @ Wh (M=2048, N=1024, K=1024), z selects W.
// BM=128, BN=64, BK=32. 256 threads = 8 warps (4x2), warp tile 32x32.
// ---------------------------------------------------------------------------
__global__ __launch_bounds__(256) void qkv_gemm_kernel()
{
    constexpr int BM = 128, BN = 64, BK = 32;
    const __half* W = g_wh[blockIdx.z];
    __half*       Y = (blockIdx.z == 0) ? g_qh : (blockIdx.z == 1) ? g_kh : g_vh;

    __shared__ __align__(16) __half As[BM][BK + 8];
    __shared__ __align__(16) __half Bs[BK][BN + 8];
    __shared__ __align__(16) float  Cs[BM][BN + 4];

    const int tid  = threadIdx.x;
    const int warp = tid >> 5;
    const int wm   = warp & 3;
    const int wn   = warp >> 2;

    const int row0 = blockIdx.y * BM;
    const int col0 = blockIdx.x * BN;

    wmma::fragment<wmma::accumulator, 16, 16, 16, float> acc[2][2];
    #pragma unroll
    for (int i = 0; i < 2; i++)
        #pragma unroll
        for (int j = 0; j < 2; j++)
            wmma::fill_fragment(acc[i][j], 0.0f);

    for (int k0 = 0; k0 < DM; k0 += BK) {
        #pragma unroll
        for (int it = 0; it < 2; it++) {
            int idx = tid + it * 256;
            int r = idx >> 2, c = idx & 3;
            *(int4*)&As[r][c * 8] =
                *(const int4*)&g_xh[(size_t)(row0 + r) * DM + k0 + c * 8];
        }
        {
            int r = tid >> 3, c = tid & 7;
            *(int4*)&Bs[r][c * 8] =
                *(const int4*)&W[(size_t)(k0 + r) * DM + col0 + c * 8];
        }
        __syncthreads();

        #pragma unroll
        for (int kk = 0; kk < BK; kk += 16) {
            wmma::fragment<wmma::matrix_a, 16, 16, 16, __half, wmma::row_major> a[2];
            wmma::fragment<wmma::matrix_b, 16, 16, 16, __half, wmma::row_major> b[2];
            #pragma unroll
            for (int i = 0; i < 2; i++)
                wmma::load_matrix_sync(a[i], &As[wm * 32 + i * 16][kk], BK + 8);
            #pragma unroll
            for (int j = 0; j < 2; j++)
                wmma::load_matrix_sync(b[j], &Bs[kk][wn * 32 + j * 16], BN + 8);
            #pragma unroll
            for (int i = 0; i < 2; i++)
                #pragma unroll
                for (int j = 0; j < 2; j++)
                    wmma::mma_sync(acc[i][j], a[i], b[j], acc[i][j]);
        }
        __syncthreads();
    }

    // Stage fp32 accumulators to smem, convert to half, coalesced store.
    #pragma unroll
    for (int i = 0; i < 2; i++)
        #pragma unroll
        for (int j = 0; j < 2; j++)
            wmma::store_matrix_sync(&Cs[wm * 32 + i * 16][wn * 32 + j * 16],
                                    acc[i][j], BN + 4, wmma::mem_row_major);
    __syncthreads();

    // 128 x 64 halves = 2048 groups of 4, 8 per thread
    #pragma unroll
    for (int it = 0; it < 8; it++) {
        int idx = tid + it * 256;
        int r = idx >> 4, c4 = idx & 15;
        float4 v = *(const float4*)&Cs[r][c4 * 4];
        __half2 h0 = __floats2half2_rn(v.x, v.y);
        __half2 h1 = __floats2half2_rn(v.z, v.w);
        uint2 u;
        u.x = *(const uint32_t*)&h0;
        u.y = *(const uint32_t*)&h1;
        *(uint2*)&Y[(size_t)(row0 + r) * DM + col0 + c4 * 4] = u;
    }
}

// ---------------------------------------------------------------------------
// Kernel 2: e[h][q][k] = exp(q_h . k_h / 8)  (unnormalized), fp16 operands.
// 128x128 tile per block. 8 warps (4x2), warp tile 32x64.
// Also emits per-(row, ktile) partial sums for the softmax denominator.
// ---------------------------------------------------------------------------
__global__ __launch_bounds__(256) void scores_exp_kernel(float* __restrict__ probs)
{
    const int h = blockIdx.z;
    __shared__ __align__(16) __half Qs[128][HD + 8];
    __shared__ __align__(16) __half Ks[128][HD + 8];
    __shared__ __align__(16) float  Ss[128][132];

    const int tid  = threadIdx.x;
    const int warp = tid >> 5;
    const int wm   = warp & 3;   // 4 strips of 32 q-rows
    const int wn   = warp >> 2;  // 2 strips of 64 k-cols

    const int qrow0 = blockIdx.y * 128;
    const int krow0 = blockIdx.x * 128;
    const __half* qp = g_qh + h * HD;
    const __half* kp = g_kh + h * HD;

    #pragma unroll
    for (int it = 0; it < 4; it++) {
        int idx = tid + it * 256;
        int r = idx >> 3, c = idx & 7;
        *(int4*)&Qs[r][c * 8] =
            *(const int4*)&qp[(size_t)(qrow0 + r) * DM + c * 8];
        *(int4*)&Ks[r][c * 8] =
            *(const int4*)&kp[(size_t)(krow0 + r) * DM + c * 8];
    }
    __syncthreads();

    wmma::fragment<wmma::accumulator, 16, 16, 16, float> acc[2][4];
    #pragma unroll
    for (int i = 0; i < 2; i++)
        #pragma unroll
        for (int j = 0; j < 4; j++)
            wmma::fill_fragment(acc[i][j], 0.0f);

    #pragma unroll
    for (int kk = 0; kk < HD; kk += 16) {
        wmma::fragment<wmma::matrix_a, 16, 16, 16, __half, wmma::row_major> a[2];
        wmma::fragment<wmma::matrix_b, 16, 16, 16, __half, wmma::col_major> b[4];
        #pragma unroll
        for (int i = 0; i < 2; i++)
            wmma::load_matrix_sync(a[i], &Qs[wm * 32 + i * 16][kk], HD + 8);
        #pragma unroll
        for (int j = 0; j < 4; j++)
            wmma::load_matrix_sync(b[j], &Ks[wn * 64 + j * 16][kk], HD + 8);
        #pragma unroll
        for (int i = 0; i < 2; i++)
            #pragma unroll
            for (int j = 0; j < 4; j++)
                wmma::mma_sync(acc[i][j], a[i], b[j], acc[i][j]);
    }

    // Stage scaled scores to smem.
    #pragma unroll
    for (int i = 0; i < 2; i++)
        #pragma unroll
        for (int j = 0; j < 4; j++) {
            #pragma unroll
            for (int e = 0; e < acc[i][j].num_elements; e++)
                acc[i][j].x[e] *= 0.125f;   // 1/sqrt(64)
            wmma::store_matrix_sync(&Ss[wm * 32 + i * 16][wn * 64 + j * 16],
                                    acc[i][j], 132, wmma::mem_row_major);
        }
    __syncthreads();

    // exp in place + row partial sums (2 threads per row, 64 cols each).
    {
        int r = tid >> 1;
        int c0 = (tid & 1) * 64;
        float s = 0.0f;
        #pragma unroll
        for (int i = 0; i < 16; i++) {
            float4 v = *(const float4*)&Ss[r][c0 + i * 4];
            v.x = __expf(v.x); v.y = __expf(v.y);
            v.z = __expf(v.z); v.w = __expf(v.w);
            s += (v.x + v.y) + (v.z + v.w);
            *(float4*)&Ss[r][c0 + i * 4] = v;
        }
        s += __shfl_xor_sync(0xFFFFFFFFu, s, 1);
        if ((tid & 1) == 0)
            g_psum[((size_t)h * S_LEN + qrow0 + r) * 16 + blockIdx.x] = s;
    }
    __syncthreads();

    // Coalesced write of e-tile to gmem (probs region, unnormalized).
    float* outp = probs + (size_t)h * S_LEN * S_LEN;
    #pragma unroll
    for (int it = 0; it < 16; it++) {
        int idx = tid + it * 256;
        int r = idx >> 5, c4 = idx & 31;
        *(float4*)&outp[(size_t)(qrow0 + r) * S_LEN + krow0 + c4 * 4] =
            *(const float4*)&Ss[r][c4 * 4];
    }
}

// ---------------------------------------------------------------------------
// Kernel 3: rowsum -> reciprocal. One thread per (head, row). Deterministic.
// ---------------------------------------------------------------------------
__global__ __launch_bounds__(256) void rowsum_kernel()
{
    int row = blockIdx.x * 256 + threadIdx.x;   // 0 .. NH*S_LEN-1
    const float* p = &g_psum[(size_t)row * 16];
    float s = 0.0f;
    #pragma unroll
    for (int i = 0; i < 16; i++) s += p[i];
    g_rinv[row] = 1.0f / s;
}

// ---------------------------------------------------------------------------
// Kernel 4: PV + probs normalization writeback.
// Reads unnormalized e (fp32), multiplies by 1/rowsum, writes normalized
// probs back in place, uses half version for the MMA.
// BM=128, BK=64. 8 warps (4x2), warp tile 32x32. grid = (16 qstrips, 16 heads).
// ---------------------------------------------------------------------------
__global__ __launch_bounds__(256) void pv_kernel(
    float* __restrict__ probs, float* __restrict__ ctx)
{
    constexpr int BM = 128, BK = 64;
    const int h = blockIdx.y;
    float* P = probs + (size_t)h * S_LEN * S_LEN;
    const __half* vp = g_vh + h * HD;

    __shared__ __align__(16) __half Ps[BM][BK + 8];
    __shared__ __align__(16) __half Vs[BK][HD + 8];
    __shared__ float rinv[BM];

    const int tid  = threadIdx.x;
    const int warp = tid >> 5;
    const int wm   = warp & 3;
    const int wn   = warp >> 2;
    const int row0 = blockIdx.x * BM;

    if (tid < BM)
        rinv[tid] = g_rinv[(size_t)h * S_LEN + row0 + tid];
    __syncthreads();

    wmma::fragment<wmma::accumulator, 16, 16, 16, float> acc[2][2];
    #pragma unroll
    for (int i = 0; i < 2; i++)
        #pragma unroll
        for (int j = 0; j < 2; j++)
            wmma::fill_fragment(acc[i][j], 0.0f);

    for (int k0 = 0; k0 < S_LEN; k0 += BK) {
        // P tile: 128 rows x 16 float4 = 2048, 8 per thread.
        // Normalize, write back normalized probs, convert to half for mma.
        #pragma unroll
        for (int it = 0; it < 8; it++) {
            int idx = tid + it * 256;
            int r = idx >> 4, c4 = idx & 15;
            float* gp = &P[(size_t)(row0 + r) * S_LEN + k0 + c4 * 4];
            float4 v = *(const float4*)gp;
            float iv = rinv[r];
            v.x *= iv; v.y *= iv; v.z *= iv; v.w *= iv;
            *(float4*)gp = v;
            __half2 h0 = __floats2half2_rn(v.x, v.y);
            __half2 h1 = __floats2half2_rn(v.z, v.w);
            uint2 u;
            u.x = *(const uint32_t*)&h0;
            u.y = *(const uint32_t*)&h1;
            *(uint2*)&Ps[r][c4 * 4] = u;
        }
        // V tile: 64 rows x 8 int4 = 512, 2/thread
        #pragma unroll
        for (int it = 0; it < 2; it++) {
            int idx = tid + it * 256;
            int r = idx >> 3, c = idx & 7;
            *(int4*)&Vs[r][c * 8] =
                *(const int4*)&vp[(size_t)(k0 + r) * DM + c * 8];
        }
        __syncthreads();

        #pragma unroll
        for (int kk = 0; kk < BK; kk += 16) {
            wmma::fragment<wmma::matrix_a, 16, 16, 16, __half, wmma::row_major> a[2];
            wmma::fragment<wmma::matrix_b, 16, 16, 16, __half, wmma::row_major> b[2];
            #pragma unroll
            for (int i = 0; i < 2; i++)
                wmma::load_matrix_sync(a[i], &Ps[wm * 32 + i * 16][kk], BK + 8);
            #pragma unroll
            for (int j = 0; j < 2; j++)
                wmma::load_matrix_sync(b[j], &Vs[kk][wn * 32 + j * 16], HD + 8);
            #pragma unroll
            for (int i = 0; i < 2; i++)
                #pragma unroll
                for (int j = 0; j < 2; j++)
                    wmma::mma_sync(acc[i][j], a[i], b[j], acc[i][j]);
        }
        __syncthreads();
    }

    #pragma unroll
    for (int i = 0; i < 2; i++)
        #pragma unroll
        for (int j = 0; j < 2; j++)
            wmma::store_matrix_sync(
                &ctx[(size_t)(row0 + wm * 32 + i * 16) * DM + h * HD +
                     wn * 32 + j * 16],
                acc[i][j], DM, wmma::mem_row_major);
}

// ---------------------------------------------------------------------------
// Launch. d_out layout: context (2048*1024 floats) then probs (16*2048*2048).
// ---------------------------------------------------------------------------
extern "C" void kernel_launch(void* const* d_in, const int* in_sizes, int n_in,
                              void* d_out, int out_size)
{
    const float* hs = (const float*)d_in[0];
    const float* Wq = (const float*)d_in[1];
    const float* Wk = (const float*)d_in[2];
    const float* Wv = (const float*)d_in[3];

    float* ctx   = (float*)d_out;
    float* probs = ctx + (size_t)S_LEN * DM;

    cvt_x_kernel<<<dim3(S_LEN * DM / 4 / 256), 256>>>(hs);
    cvt_w_kernel<<<dim3(DM * DM / 4 / 256, 1, 3), 256>>>(Wq, Wk, Wv);
    qkv_gemm_kernel<<<dim3(DM / 64, S_LEN / 128, 3), 256>>>();
    scores_exp_kernel<<<dim3(S_LEN / 128, S_LEN / 128, NH), 256>>>(probs);
    rowsum_kernel<<<dim3(NH * S_LEN / 256), 256>>>();
    pv_kernel<<<dim3(S_LEN / 128, NH), 256>>>(probs, ctx);
}

// round 7
// speedup vs baseline: 1.2862x; 1.2862x over previous
#include <cuda_runtime.h>
#include <cuda_fp16.h>
#include <mma.h>
#include <math.h>
#include <cstdint>

using namespace nvcuda;

#define S_LEN 2048
#define DM    1024
#define NH    16
#define HD    64

// Scratch (allocation-guard rules: __device__ globals).
__device__ __half g_xh[S_LEN * DM];
__device__ __half g_wh[3][DM * DM];
__device__ __half g_qh[S_LEN * DM];
__device__ __half g_kh[S_LEN * DM];
__device__ __half g_vh[S_LEN * DM];
__device__ __half g_eh[(size_t)NH * S_LEN * S_LEN];  // unnormalized exp(scores), half
__device__ float  g_psum[NH * S_LEN * 16];           // per-(row, ktile) partial sums
__device__ float  g_rinv[NH * S_LEN];                // 1 / rowsum

// ---------------------------------------------------------------------------
// fp32 -> fp16 converters.
// ---------------------------------------------------------------------------
__device__ __forceinline__ void cvt4(const float* __restrict__ src,
                                     __half* __restrict__ dst, size_t i)
{
    float4 v = ((const float4*)src)[i];
    __half2 a = __floats2half2_rn(v.x, v.y);
    __half2 b = __floats2half2_rn(v.z, v.w);
    uint2 u;
    u.x = *(const uint32_t*)&a;
    u.y = *(const uint32_t*)&b;
    ((uint2*)dst)[i] = u;
}

__global__ __launch_bounds__(256) void cvt_x_kernel(const float* __restrict__ X)
{
    cvt4(X, g_xh, (size_t)blockIdx.x * 256 + threadIdx.x);
}

__global__ __launch_bounds__(256) void cvt_w_kernel(
    const float* __restrict__ Wq, const float* __restrict__ Wk,
    const float* __restrict__ Wv)
{
    const float* src = (blockIdx.z == 0) ? Wq : (blockIdx.z == 1) ? Wk : Wv;
    cvt4(src, g_wh[blockIdx.z], (size_t)blockIdx.x * 256 + threadIdx.x);
}

// ---------------------------------------------------------------------------
// Kernel 1: QKV projection, fp16 in / fp32 accum / fp16 out (smem-staged).
// BM=128, BN=64, BK=32. 256 threads = 8 warps (4x2), warp tile 32x32.
// ---------------------------------------------------------------------------
__global__ __launch_bounds__(256) void qkv_gemm_kernel()
{
    constexpr int BM = 128, BN = 64, BK = 32;
    const __half* W = g_wh[blockIdx.z];
    __half*       Y = (blockIdx.z == 0) ? g_qh : (blockIdx.z == 1) ? g_kh : g_vh;

    __shared__ __align__(16) __half As[BM][BK + 8];
    __shared__ __align__(16) __half Bs[BK][BN + 8];
    __shared__ __align__(16) float  Cs[BM][BN + 4];

    const int tid  = threadIdx.x;
    const int warp = tid >> 5;
    const int wm   = warp & 3;
    const int wn   = warp >> 2;

    const int row0 = blockIdx.y * BM;
    const int col0 = blockIdx.x * BN;

    wmma::fragment<wmma::accumulator, 16, 16, 16, float> acc[2][2];
    #pragma unroll
    for (int i = 0; i < 2; i++)
        #pragma unroll
        for (int j = 0; j < 2; j++)
            wmma::fill_fragment(acc[i][j], 0.0f);

    for (int k0 = 0; k0 < DM; k0 += BK) {
        #pragma unroll
        for (int it = 0; it < 2; it++) {
            int idx = tid + it * 256;
            int r = idx >> 2, c = idx & 3;
            *(int4*)&As[r][c * 8] =
                *(const int4*)&g_xh[(size_t)(row0 + r) * DM + k0 + c * 8];
        }
        {
            int r = tid >> 3, c = tid & 7;
            *(int4*)&Bs[r][c * 8] =
                *(const int4*)&W[(size_t)(k0 + r) * DM + col0 + c * 8];
        }
        __syncthreads();

        #pragma unroll
        for (int kk = 0; kk < BK; kk += 16) {
            wmma::fragment<wmma::matrix_a, 16, 16, 16, __half, wmma::row_major> a[2];
            wmma::fragment<wmma::matrix_b, 16, 16, 16, __half, wmma::row_major> b[2];
            #pragma unroll
            for (int i = 0; i < 2; i++)
                wmma::load_matrix_sync(a[i], &As[wm * 32 + i * 16][kk], BK + 8);
            #pragma unroll
            for (int j = 0; j < 2; j++)
                wmma::load_matrix_sync(b[j], &Bs[kk][wn * 32 + j * 16], BN + 8);
            #pragma unroll
            for (int i = 0; i < 2; i++)
                #pragma unroll
                for (int j = 0; j < 2; j++)
                    wmma::mma_sync(acc[i][j], a[i], b[j], acc[i][j]);
        }
        __syncthreads();
    }

    #pragma unroll
    for (int i = 0; i < 2; i++)
        #pragma unroll
        for (int j = 0; j < 2; j++)
            wmma::store_matrix_sync(&Cs[wm * 32 + i * 16][wn * 32 + j * 16],
                                    acc[i][j], BN + 4, wmma::mem_row_major);
    __syncthreads();

    #pragma unroll
    for (int it = 0; it < 8; it++) {
        int idx = tid + it * 256;
        int r = idx >> 4, c4 = idx & 15;
        float4 v = *(const float4*)&Cs[r][c4 * 4];
        __half2 h0 = __floats2half2_rn(v.x, v.y);
        __half2 h1 = __floats2half2_rn(v.z, v.w);
        uint2 u;
        u.x = *(const uint32_t*)&h0;
        u.y = *(const uint32_t*)&h1;
        *(uint2*)&Y[(size_t)(row0 + r) * DM + col0 + c4 * 4] = u;
    }
}

// ---------------------------------------------------------------------------
// Kernel 2: e = exp(q.k/8) (unnormalized), written as HALF to g_eh.
// 128x128 tile, 8 warps (4x2), warp tile 32x64. exp applied in registers.
// Smem: Q/K tiles overlaid (union) with the fp32 stage used by the epilogue.
// Emits per-(row, ktile) fp32 partial sums.
// ---------------------------------------------------------------------------
__global__ __launch_bounds__(256) void scores_exp_kernel()
{
    const int h = blockIdx.z;
    __shared__ __align__(16) union {
        struct { __half Q[128][HD + 8]; __half K[128][HD + 8]; } in;
        float S[128][132];
    } u;

    const int tid  = threadIdx.x;
    const int warp = tid >> 5;
    const int wm   = warp & 3;   // 4 strips of 32 q-rows
    const int wn   = warp >> 2;  // 2 strips of 64 k-cols

    const int qrow0 = blockIdx.y * 128;
    const int krow0 = blockIdx.x * 128;
    const __half* qp = g_qh + h * HD;
    const __half* kp = g_kh + h * HD;

    #pragma unroll
    for (int it = 0; it < 4; it++) {
        int idx = tid + it * 256;
        int r = idx >> 3, c = idx & 7;
        *(int4*)&u.in.Q[r][c * 8] =
            *(const int4*)&qp[(size_t)(qrow0 + r) * DM + c * 8];
        *(int4*)&u.in.K[r][c * 8] =
            *(const int4*)&kp[(size_t)(krow0 + r) * DM + c * 8];
    }
    __syncthreads();

    wmma::fragment<wmma::accumulator, 16, 16, 16, float> acc[2][4];
    #pragma unroll
    for (int i = 0; i < 2; i++)
        #pragma unroll
        for (int j = 0; j < 4; j++)
            wmma::fill_fragment(acc[i][j], 0.0f);

    #pragma unroll
    for (int kk = 0; kk < HD; kk += 16) {
        wmma::fragment<wmma::matrix_a, 16, 16, 16, __half, wmma::row_major> a[2];
        wmma::fragment<wmma::matrix_b, 16, 16, 16, __half, wmma::col_major> b[4];
        #pragma unroll
        for (int i = 0; i < 2; i++)
            wmma::load_matrix_sync(a[i], &u.in.Q[wm * 32 + i * 16][kk], HD + 8);
        #pragma unroll
        for (int j = 0; j < 4; j++)
            wmma::load_matrix_sync(b[j], &u.in.K[wn * 64 + j * 16][kk], HD + 8);
        #pragma unroll
        for (int i = 0; i < 2; i++)
            #pragma unroll
            for (int j = 0; j < 4; j++)
                wmma::mma_sync(acc[i][j], a[i], b[j], acc[i][j]);
    }

    // exp in registers, then stage fp32 (Q/K tiles are dead -> reuse smem).
    __syncthreads();
    #pragma unroll
    for (int i = 0; i < 2; i++)
        #pragma unroll
        for (int j = 0; j < 4; j++) {
            #pragma unroll
            for (int e = 0; e < acc[i][j].num_elements; e++)
                acc[i][j].x[e] = __expf(acc[i][j].x[e] * 0.125f);
            wmma::store_matrix_sync(&u.S[wm * 32 + i * 16][wn * 64 + j * 16],
                                    acc[i][j], 132, wmma::mem_row_major);
        }
    __syncthreads();

    // Phase A: fp32 row partial sums (2 threads per row, 64 cols each).
    {
        int r = tid >> 1;
        int c0 = (tid & 1) * 64;
        float s = 0.0f;
        #pragma unroll
        for (int i = 0; i < 16; i++) {
            float4 v = *(const float4*)&u.S[r][c0 + i * 4];
            s += (v.x + v.y) + (v.z + v.w);
        }
        s += __shfl_xor_sync(0xFFFFFFFFu, s, 1);
        if ((tid & 1) == 0)
            g_psum[((size_t)h * S_LEN + qrow0 + r) * 16 + blockIdx.x] = s;
    }

    // Phase B: coalesced HALF write of the e-tile.
    __half* outp = g_eh + (size_t)h * S_LEN * S_LEN;
    #pragma unroll
    for (int it = 0; it < 8; it++) {
        int idx = tid + it * 256;        // 128 rows x 16 uint4 (8 halfs each)
        int r = idx >> 4, c = idx & 15;
        float4 v0 = *(const float4*)&u.S[r][c * 8];
        float4 v1 = *(const float4*)&u.S[r][c * 8 + 4];
        __half2 h0 = __floats2half2_rn(v0.x, v0.y);
        __half2 h1 = __floats2half2_rn(v0.z, v0.w);
        __half2 h2 = __floats2half2_rn(v1.x, v1.y);
        __half2 h3 = __floats2half2_rn(v1.z, v1.w);
        uint4 o;
        o.x = *(const uint32_t*)&h0;
        o.y = *(const uint32_t*)&h1;
        o.z = *(const uint32_t*)&h2;
        o.w = *(const uint32_t*)&h3;
        *(uint4*)&outp[(size_t)(qrow0 + r) * S_LEN + krow0 + c * 8] = o;
    }
}

// ---------------------------------------------------------------------------
// Kernel 3: rowsum -> reciprocal. One thread per (head, row). Deterministic.
// ---------------------------------------------------------------------------
__global__ __launch_bounds__(256) void rowsum_kernel()
{
    int row = blockIdx.x * 256 + threadIdx.x;
    const float* p = &g_psum[(size_t)row * 16];
    float s = 0.0f;
    #pragma unroll
    for (int i = 0; i < 16; i++) s += p[i];
    g_rinv[row] = 1.0f / s;
}

// ---------------------------------------------------------------------------
// Kernel 4: finalize probs: probs[row][k] = half_e[row][k] * rinv[row].
// One block per (head,row). Reads 8 halfs / writes 8 floats per thread.
// ---------------------------------------------------------------------------
__global__ __launch_bounds__(256) void finalize_kernel(float* __restrict__ probs)
{
    const size_t row = blockIdx.x;
    const float rinv = g_rinv[row];
    const uint4* src = (const uint4*)(g_eh + row * S_LEN);
    float4* dst = (float4*)(probs + row * S_LEN);
    const int tid = threadIdx.x;

    uint4 uv = src[tid];
    __half2 h0 = *(const __half2*)&uv.x;
    __half2 h1 = *(const __half2*)&uv.y;
    __half2 h2 = *(const __half2*)&uv.z;
    __half2 h3 = *(const __half2*)&uv.w;
    float2 f0 = __half22float2(h0);
    float2 f1 = __half22float2(h1);
    float2 f2 = __half22float2(h2);
    float2 f3 = __half22float2(h3);
    dst[2 * tid]     = make_float4(f0.x * rinv, f0.y * rinv, f1.x * rinv, f1.y * rinv);
    dst[2 * tid + 1] = make_float4(f2.x * rinv, f2.y * rinv, f3.x * rinv, f3.y * rinv);
}

// ---------------------------------------------------------------------------
// Kernel 5: PV on unnormalized half e; row scaling by rinv applied to the
// output through an smem stage. BM=128, BK=64. 8 warps (4x2), warp tile 32x32.
// ---------------------------------------------------------------------------
__global__ __launch_bounds__(256) void pv_kernel(float* __restrict__ ctx)
{
    constexpr int BM = 128, BK = 64;
    const int h = blockIdx.y;
    const __half* E  = g_eh + (size_t)h * S_LEN * S_LEN;
    const __half* vp = g_vh + h * HD;

    __shared__ __align__(16) union {
        struct { __half P[BM][BK + 8]; __half V[BK][HD + 8]; } in;
        float C[BM][HD + 4];
    } u;
    __shared__ float rinv[BM];

    const int tid  = threadIdx.x;
    const int warp = tid >> 5;
    const int wm   = warp & 3;
    const int wn   = warp >> 2;
    const int row0 = blockIdx.x * BM;

    if (tid < BM)
        rinv[tid] = g_rinv[(size_t)h * S_LEN + row0 + tid];

    wmma::fragment<wmma::accumulator, 16, 16, 16, float> acc[2][2];
    #pragma unroll
    for (int i = 0; i < 2; i++)
        #pragma unroll
        for (int j = 0; j < 2; j++)
            wmma::fill_fragment(acc[i][j], 0.0f);

    for (int k0 = 0; k0 < S_LEN; k0 += BK) {
        // P tile: 128 rows x 8 int4 = 1024, 4/thread
        #pragma unroll
        for (int it = 0; it < 4; it++) {
            int idx = tid + it * 256;
            int r = idx >> 3, c = idx & 7;
            *(int4*)&u.in.P[r][c * 8] =
                *(const int4*)&E[(size_t)(row0 + r) * S_LEN + k0 + c * 8];
        }
        // V tile: 64 rows x 8 int4 = 512, 2/thread
        #pragma unroll
        for (int it = 0; it < 2; it++) {
            int idx = tid + it * 256;
            int r = idx >> 3, c = idx & 7;
            *(int4*)&u.in.V[r][c * 8] =
                *(const int4*)&vp[(size_t)(k0 + r) * DM + c * 8];
        }
        __syncthreads();

        #pragma unroll
        for (int kk = 0; kk < BK; kk += 16) {
            wmma::fragment<wmma::matrix_a, 16, 16, 16, __half, wmma::row_major> a[2];
            wmma::fragment<wmma::matrix_b, 16, 16, 16, __half, wmma::row_major> b[2];
            #pragma unroll
            for (int i = 0; i < 2; i++)
                wmma::load_matrix_sync(a[i], &u.in.P[wm * 32 + i * 16][kk], BK + 8);
            #pragma unroll
            for (int j = 0; j < 2; j++)
                wmma::load_matrix_sync(b[j], &u.in.V[kk][wn * 32 + j * 16], HD + 8);
            #pragma unroll
            for (int i = 0; i < 2; i++)
                #pragma unroll
                for (int j = 0; j < 2; j++)
                    wmma::mma_sync(acc[i][j], a[i], b[j], acc[i][j]);
        }
        __syncthreads();
    }

    // Stage, scale rows by rinv, coalesced store.
    #pragma unroll
    for (int i = 0; i < 2; i++)
        #pragma unroll
        for (int j = 0; j < 2; j++)
            wmma::store_matrix_sync(&u.C[wm * 32 + i * 16][wn * 32 + j * 16],
                                    acc[i][j], HD + 4, wmma::mem_row_major);
    __syncthreads();

    #pragma unroll
    for (int it = 0; it < 8; it++) {
        int idx = tid + it * 256;        // 128 rows x 16 float4
        int r = idx >> 4, c4 = idx & 15;
        float iv = rinv[r];
        float4 v = *(const float4*)&u.C[r][c4 * 4];
        v.x *= iv; v.y *= iv; v.z *= iv; v.w *= iv;
        *(float4*)&ctx[(size_t)(row0 + r) * DM + h * HD + c4 * 4] = v;
    }
}

// ---------------------------------------------------------------------------
// Launch. d_out layout: context (2048*1024 floats) then probs (16*2048*2048).
// ---------------------------------------------------------------------------
extern "C" void kernel_launch(void* const* d_in, const int* in_sizes, int n_in,
                              void* d_out, int out_size)
{
    const float* hs = (const float*)d_in[0];
    const float* Wq = (const float*)d_in[1];
    const float* Wk = (const float*)d_in[2];
    const float* Wv = (const float*)d_in[3];

    float* ctx   = (float*)d_out;
    float* probs = ctx + (size_t)S_LEN * DM;

    cvt_x_kernel<<<dim3(S_LEN * DM / 4 / 256), 256>>>(hs);
    cvt_w_kernel<<<dim3(DM * DM / 4 / 256, 1, 3), 256>>>(Wq, Wk, Wv);
    qkv_gemm_kernel<<<dim3(DM / 64, S_LEN / 128, 3), 256>>>();
    scores_exp_kernel<<<dim3(S_LEN / 128, S_LEN / 128, NH), 256>>>();
    rowsum_kernel<<<dim3(NH * S_LEN / 256), 256>>>();
    pv_kernel<<<dim3(S_LEN / 128, NH), 256>>>(ctx);
    finalize_kernel<<<dim3(NH * S_LEN), 256>>>(probs);
}